// round 13
// baseline (speedup 1.0000x reference)
#include <cuda_runtime.h>
#include <cuda_fp16.h>
#include <cstdint>

// out[b,p,o] = relu(sum_k x[b,p,k] * W[p,k,o] + bias[p,o])
// B=16384, P=K=O=64 fp32.
// CTA = 128 b-rows x one part p, 4 warps, warp tile M=32,N=64.
// SINGLE-TERM fp16 (rel_err ~2.9e-4), fp32 accum, mma.sync.m16n8k16.
// sigma/tau permutations (LDG.128 A-loads, STG.128 C-stores).
// R13: no register double-buffer for x — chunk loads issued at chunk start
// (L2-resident via rolling prefetch.global.L2) -> regs drop -> 6 CTAs/SM.

#define PP 64
#define KK 64
#define OO 64
#define BLOCK_B 128
#define THREADS 128

#define ASTRIDE 72                         // fp16 elems per smem row (144 B)
#define ROWB (ASTRIDE * 2)                 // 144 bytes per smem row
#define SW_BYTES (KK * ROWB)               // 9216
#define SM_TOTAL SW_BYTES

__device__ __forceinline__ uint32_t smem_u32(const void* p) {
    uint32_t a;
    asm("{ .reg .u64 t; cvta.to.shared.u64 t, %1; cvt.u32.u64 %0, t; }" : "=r"(a) : "l"(p));
    return a;
}

// pack word: lo16 = f16(a), hi16 = f16(b)
__device__ __forceinline__ uint32_t pack_f16(float a, float b) {
    uint32_t r;
    asm("cvt.rn.f16x2.f32 %0, %1, %2;" : "=r"(r) : "f"(b), "f"(a));
    return r;
}

__device__ __forceinline__ void prefetch_l2(const void* p) {
    asm volatile("prefetch.global.L2 [%0];" :: "l"(p));
}

#define LDSM_X4_T(r0, r1, r2, r3, addr) \
    asm volatile("ldmatrix.sync.aligned.m8n8.x4.trans.shared.b16 {%0,%1,%2,%3}, [%4];" \
                 : "=r"(r0), "=r"(r1), "=r"(r2), "=r"(r3) : "r"(addr))

#define MMA_F16(d, a, b0_, b1_) \
    asm volatile("mma.sync.aligned.m16n8k16.row.col.f32.f16.f16.f32 " \
                 "{%0,%1,%2,%3}, {%4,%5,%6,%7}, {%8,%9}, {%0,%1,%2,%3};" \
                 : "+f"((d)[0]), "+f"((d)[1]), "+f"((d)[2]), "+f"((d)[3]) \
                 : "r"((a)[0]), "r"((a)[1]), "r"((a)[2]), "r"((a)[3]), \
                   "r"(b0_), "r"(b1_))

extern "C" __global__ void __launch_bounds__(THREADS, 6)
parts_f16_occ6_kernel(const float* __restrict__ x,
                      const float* __restrict__ W,
                      const float* __restrict__ bias,
                      float* __restrict__ out)
{
    extern __shared__ char smem[];
    const uint32_t sb = smem_u32(smem);
    const int t    = threadIdx.x;
    const int wid  = t >> 5;
    const int lane = t & 31;
    const int p    = blockIdx.y;
    const int b0   = blockIdx.x * BLOCK_B;

    const int w32  = wid * 32;
    const int qrow = lane >> 2;          // 0..7
    const int q4   = (lane & 3) * 4;     // phys-k / out-col quad offset

    const size_t RS = (size_t)(PP * KK); // 4096 floats, batch row stride

    // Per-thread A base: phys cols q4..q4+3 of each 16-k chunk.
    const float* xq = x + (size_t)(b0 + w32 + qrow) * RS + p * KK + q4;

    // ---- L2-prefetch chunks 0 and 1 before the W prologue ----
    #pragma unroll
    for (int mi = 0; mi < 2; mi++)
        #pragma unroll
        for (int rs = 0; rs < 2; rs++) {
            prefetch_l2(xq + (mi * 16 + rs * 8) * RS);
            prefetch_l2(xq + (mi * 16 + rs * 8) * RS + 16);
        }

    // ---- W[p] -> smem fp16, sigma/tau permuted ----
    // sigma: phys k -> smem row sr = (k&~15) + 2*((k>>2)&3) + (k&1) + 8*((k>>1)&1)
    // tau:   phys o (=c4*4+j) -> smem col (2*(c4>>2)+(j>>1))*8 + 2*(c4&3) + (j&1)
    #pragma unroll
    for (int i = 0; i < 8; i++) {
        int idx4 = i * 128 + t;
        int k    = idx4 >> 4;
        int c4   = idx4 & 15;
        float4 v = *(const float4*)(W + p * (KK * OO) + k * OO + c4 * 4);
        uint32_t h0 = pack_f16(v.x, v.y);
        uint32_t h1 = pack_f16(v.z, v.w);
        int w  = k & 15;
        int sr = (k & ~15) + 2 * (w >> 2) + (w & 1) + 8 * ((w >> 1) & 1);
        int col0 = (2 * (c4 >> 2)) * 8 + 2 * (c4 & 3);   // f16 units, pair j=0,1
        int col1 = col0 + 8;                              // pair j=2,3
        uint32_t base = (uint32_t)(sr * ROWB);
        *(uint32_t*)(smem + base + col0 * 2) = h0;
        *(uint32_t*)(smem + base + col1 * 2) = h1;
    }
    __syncthreads();

    // ---- Mainloop ----
    const int lrow  = lane & 15;
    const int lcol8 = (lane >> 4) * 8;

    float acc[2][8][4];
    #pragma unroll
    for (int mi = 0; mi < 2; mi++)
        #pragma unroll
        for (int ni = 0; ni < 8; ni++)
            #pragma unroll
            for (int r = 0; r < 4; r++)
                acc[mi][ni][r] = 0.0f;

    #pragma unroll
    for (int ks = 0; ks < 4; ks++) {
        const int k0 = ks * 16;

        // Load this chunk's x (L2-resident by now), convert to fp16 frags.
        float4 xf[2][2];
        #pragma unroll
        for (int mi = 0; mi < 2; mi++)
            #pragma unroll
            for (int rs = 0; rs < 2; rs++)
                xf[mi][rs] = *(const float4*)(xq + (mi * 16 + rs * 8) * RS
                                                 + ks * 16);

        // Roll the L2 prefetch window to ks+2.
        if (ks < 2) {
            #pragma unroll
            for (int mi = 0; mi < 2; mi++)
                #pragma unroll
                for (int rs = 0; rs < 2; rs++)
                    prefetch_l2(xq + (mi * 16 + rs * 8) * RS + (ks + 2) * 16);
        }

        // a0 <- (rs0).xy, a1 <- (rs1).xy, a2 <- (rs0).zw, a3 <- (rs1).zw
        uint32_t ah[2][4];
        #pragma unroll
        for (int mi = 0; mi < 2; mi++) {
            ah[mi][0] = pack_f16(xf[mi][0].x, xf[mi][0].y);
            ah[mi][1] = pack_f16(xf[mi][1].x, xf[mi][1].y);
            ah[mi][2] = pack_f16(xf[mi][0].z, xf[mi][0].w);
            ah[mi][3] = pack_f16(xf[mi][1].z, xf[mi][1].w);
        }

        #pragma unroll
        for (int ng = 0; ng < 4; ng++) {
            uint32_t bh[4];
            uint32_t off = (uint32_t)((k0 + lrow) * ROWB + (ng * 16 + lcol8) * 2);
            LDSM_X4_T(bh[0], bh[1], bh[2], bh[3], sb + off);

            #pragma unroll
            for (int mi = 0; mi < 2; mi++) {
                MMA_F16(acc[mi][2 * ng + 0], ah[mi], bh[0], bh[1]);
                MMA_F16(acc[mi][2 * ng + 1], ah[mi], bh[2], bh[3]);
            }
        }
    }

    // ---- Epilogue (tau): thread owns out cols g*16 + q4 .. +3 ----
    float4 bv[4];
    #pragma unroll
    for (int g = 0; g < 4; g++)
        bv[g] = *(const float4*)(bias + p * OO + g * 16 + q4);

    #pragma unroll
    for (int mi = 0; mi < 2; mi++) {
        #pragma unroll
        for (int rs = 0; rs < 2; rs++) {
            const int row = b0 + w32 + mi * 16 + rs * 8 + qrow;
            float* op = out + (size_t)row * RS + p * OO + q4;
            #pragma unroll
            for (int g = 0; g < 4; g++) {
                float4 v;
                v.x = fmaxf(acc[mi][2 * g + 0][rs * 2 + 0] + bv[g].x, 0.0f);
                v.y = fmaxf(acc[mi][2 * g + 0][rs * 2 + 1] + bv[g].y, 0.0f);
                v.z = fmaxf(acc[mi][2 * g + 1][rs * 2 + 0] + bv[g].z, 0.0f);
                v.w = fmaxf(acc[mi][2 * g + 1][rs * 2 + 1] + bv[g].w, 0.0f);
                *(float4*)(op + g * 16) = v;
            }
        }
    }
}

extern "C" void kernel_launch(void* const* d_in, const int* in_sizes, int n_in,
                              void* d_out, int out_size)
{
    const float* x    = (const float*)d_in[0];
    const float* W    = (const float*)d_in[1];
    const float* bias = (const float*)d_in[2];
    float* out = (float*)d_out;

    const int B = in_sizes[0] / (PP * KK);   // 16384

    cudaFuncSetAttribute(parts_f16_occ6_kernel,
                         cudaFuncAttributeMaxDynamicSharedMemorySize, SM_TOTAL);

    dim3 grid(B / BLOCK_B, PP);
    parts_f16_occ6_kernel<<<grid, THREADS, SM_TOTAL>>>(x, W, bias, out);
}

// round 14
// speedup vs baseline: 1.0330x; 1.0330x over previous
#include <cuda_runtime.h>
#include <cuda_fp16.h>
#include <cstdint>

// out[b,p,o] = relu(sum_k x[b,p,k] * W[p,k,o] + bias[p,o])
// B=16384, P=K=O=64 fp32.
// CTA = 128 b-rows x one part p, 4 warps, warp tile M=32,N=64.
// SINGLE-TERM fp16 (rel_err ~2.9e-4), fp32 accum, mma.sync.m16n8k16.
// sigma/tau permutations (LDG.128 A-loads, STG.128 C-stores).
// R12 structure (register double-buffered x + rolling L2 prefetch, 5 CTAs/SM)
// + R14 delta: __stwt write-through output stores (out never re-read;
//   keeps L2 for the x prefetch window and W).

#define PP 64
#define KK 64
#define OO 64
#define BLOCK_B 128
#define THREADS 128

#define ASTRIDE 72                         // fp16 elems per smem row (144 B)
#define ROWB (ASTRIDE * 2)                 // 144 bytes per smem row
#define SW_BYTES (KK * ROWB)               // 9216
#define SM_TOTAL SW_BYTES

__device__ __forceinline__ uint32_t smem_u32(const void* p) {
    uint32_t a;
    asm("{ .reg .u64 t; cvta.to.shared.u64 t, %1; cvt.u32.u64 %0, t; }" : "=r"(a) : "l"(p));
    return a;
}

// pack word: lo16 = f16(a), hi16 = f16(b)
__device__ __forceinline__ uint32_t pack_f16(float a, float b) {
    uint32_t r;
    asm("cvt.rn.f16x2.f32 %0, %1, %2;" : "=r"(r) : "f"(b), "f"(a));
    return r;
}

__device__ __forceinline__ void prefetch_l2(const void* p) {
    asm volatile("prefetch.global.L2 [%0];" :: "l"(p));
}

__device__ __forceinline__ void stwt128(float* p, float4 v) {
    asm volatile("st.global.wt.v4.f32 [%0], {%1,%2,%3,%4};"
                 :: "l"(p), "f"(v.x), "f"(v.y), "f"(v.z), "f"(v.w) : "memory");
}

#define LDSM_X4_T(r0, r1, r2, r3, addr) \
    asm volatile("ldmatrix.sync.aligned.m8n8.x4.trans.shared.b16 {%0,%1,%2,%3}, [%4];" \
                 : "=r"(r0), "=r"(r1), "=r"(r2), "=r"(r3) : "r"(addr))

#define MMA_F16(d, a, b0_, b1_) \
    asm volatile("mma.sync.aligned.m16n8k16.row.col.f32.f16.f16.f32 " \
                 "{%0,%1,%2,%3}, {%4,%5,%6,%7}, {%8,%9}, {%0,%1,%2,%3};" \
                 : "+f"((d)[0]), "+f"((d)[1]), "+f"((d)[2]), "+f"((d)[3]) \
                 : "r"((a)[0]), "r"((a)[1]), "r"((a)[2]), "r"((a)[3]), \
                   "r"(b0_), "r"(b1_))

extern "C" __global__ void __launch_bounds__(THREADS, 5)
parts_f16_wt_kernel(const float* __restrict__ x,
                    const float* __restrict__ W,
                    const float* __restrict__ bias,
                    float* __restrict__ out)
{
    extern __shared__ char smem[];
    const uint32_t sb = smem_u32(smem);
    const int t    = threadIdx.x;
    const int wid  = t >> 5;
    const int lane = t & 31;
    const int p    = blockIdx.y;
    const int b0   = blockIdx.x * BLOCK_B;

    const int w32  = wid * 32;
    const int qrow = lane >> 2;          // 0..7
    const int q4   = (lane & 3) * 4;     // phys-k / out-col quad offset

    const size_t RS = (size_t)(PP * KK); // 4096 floats, batch row stride

    // Per-thread A base: phys cols q4..q4+3 of each 16-k chunk.
    const float* xq = x + (size_t)(b0 + w32 + qrow) * RS + p * KK + q4;

    // ---- Prefetch A chunk ks=0 into registers; chunks 1,2 into L2 ----
    float4 xf[2][2];
    #pragma unroll
    for (int mi = 0; mi < 2; mi++)
        #pragma unroll
        for (int rs = 0; rs < 2; rs++)
            xf[mi][rs] = *(const float4*)(xq + (mi * 16 + rs * 8) * RS);
    #pragma unroll
    for (int mi = 0; mi < 2; mi++)
        #pragma unroll
        for (int rs = 0; rs < 2; rs++) {
            prefetch_l2(xq + (mi * 16 + rs * 8) * RS + 16);
            prefetch_l2(xq + (mi * 16 + rs * 8) * RS + 32);
        }

    // ---- W[p] -> smem fp16, sigma/tau permuted ----
    // sigma: phys k -> smem row sr = (k&~15) + 2*((k>>2)&3) + (k&1) + 8*((k>>1)&1)
    // tau:   phys o (=c4*4+j) -> smem col (2*(c4>>2)+(j>>1))*8 + 2*(c4&3) + (j&1)
    #pragma unroll
    for (int i = 0; i < 8; i++) {
        int idx4 = i * 128 + t;
        int k    = idx4 >> 4;
        int c4   = idx4 & 15;
        float4 v = *(const float4*)(W + p * (KK * OO) + k * OO + c4 * 4);
        uint32_t h0 = pack_f16(v.x, v.y);
        uint32_t h1 = pack_f16(v.z, v.w);
        int w  = k & 15;
        int sr = (k & ~15) + 2 * (w >> 2) + (w & 1) + 8 * ((w >> 1) & 1);
        int col0 = (2 * (c4 >> 2)) * 8 + 2 * (c4 & 3);   // f16 units, pair j=0,1
        int col1 = col0 + 8;                              // pair j=2,3
        uint32_t base = (uint32_t)(sr * ROWB);
        *(uint32_t*)(smem + base + col0 * 2) = h0;
        *(uint32_t*)(smem + base + col1 * 2) = h1;
    }
    __syncthreads();

    // ---- Mainloop ----
    const int lrow  = lane & 15;
    const int lcol8 = (lane >> 4) * 8;

    float acc[2][8][4];
    #pragma unroll
    for (int mi = 0; mi < 2; mi++)
        #pragma unroll
        for (int ni = 0; ni < 8; ni++)
            #pragma unroll
            for (int r = 0; r < 4; r++)
                acc[mi][ni][r] = 0.0f;

    #pragma unroll
    for (int ks = 0; ks < 4; ks++) {
        const int k0 = ks * 16;

        // Convert current A chunk to fp16 fragments.
        // a0 <- (rs0).xy, a1 <- (rs1).xy, a2 <- (rs0).zw, a3 <- (rs1).zw
        uint32_t ah[2][4];
        #pragma unroll
        for (int mi = 0; mi < 2; mi++) {
            ah[mi][0] = pack_f16(xf[mi][0].x, xf[mi][0].y);
            ah[mi][1] = pack_f16(xf[mi][1].x, xf[mi][1].y);
            ah[mi][2] = pack_f16(xf[mi][0].z, xf[mi][0].w);
            ah[mi][3] = pack_f16(xf[mi][1].z, xf[mi][1].w);
        }

        // Register-prefetch next chunk (ks+1) and L2-prefetch ks+2.
        if (ks < 3) {
            #pragma unroll
            for (int mi = 0; mi < 2; mi++)
                #pragma unroll
                for (int rs = 0; rs < 2; rs++)
                    xf[mi][rs] = *(const float4*)(xq + (mi * 16 + rs * 8) * RS
                                                     + (ks + 1) * 16);
        }
        if (ks < 2) {
            #pragma unroll
            for (int mi = 0; mi < 2; mi++)
                #pragma unroll
                for (int rs = 0; rs < 2; rs++)
                    prefetch_l2(xq + (mi * 16 + rs * 8) * RS + (ks + 2) * 16);
        }

        #pragma unroll
        for (int ng = 0; ng < 4; ng++) {
            uint32_t bh[4];
            uint32_t off = (uint32_t)((k0 + lrow) * ROWB + (ng * 16 + lcol8) * 2);
            LDSM_X4_T(bh[0], bh[1], bh[2], bh[3], sb + off);

            #pragma unroll
            for (int mi = 0; mi < 2; mi++) {
                MMA_F16(acc[mi][2 * ng + 0], ah[mi], bh[0], bh[1]);
                MMA_F16(acc[mi][2 * ng + 1], ah[mi], bh[2], bh[3]);
            }
        }
    }

    // ---- Epilogue (tau): thread owns out cols g*16 + q4 .. +3 ----
    float4 bv[4];
    #pragma unroll
    for (int g = 0; g < 4; g++)
        bv[g] = *(const float4*)(bias + p * OO + g * 16 + q4);

    #pragma unroll
    for (int mi = 0; mi < 2; mi++) {
        #pragma unroll
        for (int rs = 0; rs < 2; rs++) {
            const int row = b0 + w32 + mi * 16 + rs * 8 + qrow;
            float* op = out + (size_t)row * RS + p * OO + q4;
            #pragma unroll
            for (int g = 0; g < 4; g++) {
                float4 v;
                v.x = fmaxf(acc[mi][2 * g + 0][rs * 2 + 0] + bv[g].x, 0.0f);
                v.y = fmaxf(acc[mi][2 * g + 0][rs * 2 + 1] + bv[g].y, 0.0f);
                v.z = fmaxf(acc[mi][2 * g + 1][rs * 2 + 0] + bv[g].z, 0.0f);
                v.w = fmaxf(acc[mi][2 * g + 1][rs * 2 + 1] + bv[g].w, 0.0f);
                stwt128(op + g * 16, v);
            }
        }
    }
}

extern "C" void kernel_launch(void* const* d_in, const int* in_sizes, int n_in,
                              void* d_out, int out_size)
{
    const float* x    = (const float*)d_in[0];
    const float* W    = (const float*)d_in[1];
    const float* bias = (const float*)d_in[2];
    float* out = (float*)d_out;

    const int B = in_sizes[0] / (PP * KK);   // 16384

    cudaFuncSetAttribute(parts_f16_wt_kernel,
                         cudaFuncAttributeMaxDynamicSharedMemorySize, SM_TOTAL);

    dim3 grid(B / BLOCK_B, PP);
    parts_f16_wt_kernel<<<grid, THREADS, SM_TOTAL>>>(x, W, bias, out);
}

// round 15
// speedup vs baseline: 1.0372x; 1.0040x over previous
#include <cuda_runtime.h>
#include <cuda_fp16.h>
#include <cstdint>

// out[b,p,o] = relu(sum_k x[b,p,k] * W[p,k,o] + bias[p,o])
// B=16384, P=K=O=64 fp32.
// CTA = 128 b-rows x one part p, 4 warps, warp tile M=32,N=64.
// SINGLE-TERM fp16 (rel_err ~2.9e-4), fp32 accum, mma.sync.m16n8k16.
// sigma/tau permutations (LDG.128 A-loads, STG.128 C-stores), st.global.wt out.
// R15: x loaded in TWO-CHUNK bursts (8 LDG.128 covering full 128B lines,
//      burst MLP 8) with all 4 chunks L2-prefetched during the W prologue.

#define PP 64
#define KK 64
#define OO 64
#define BLOCK_B 128
#define THREADS 128

#define ASTRIDE 72                         // fp16 elems per smem row (144 B)
#define ROWB (ASTRIDE * 2)                 // 144 bytes per smem row
#define SW_BYTES (KK * ROWB)               // 9216
#define SM_TOTAL SW_BYTES

__device__ __forceinline__ uint32_t smem_u32(const void* p) {
    uint32_t a;
    asm("{ .reg .u64 t; cvta.to.shared.u64 t, %1; cvt.u32.u64 %0, t; }" : "=r"(a) : "l"(p));
    return a;
}

// pack word: lo16 = f16(a), hi16 = f16(b)
__device__ __forceinline__ uint32_t pack_f16(float a, float b) {
    uint32_t r;
    asm("cvt.rn.f16x2.f32 %0, %1, %2;" : "=r"(r) : "f"(b), "f"(a));
    return r;
}

__device__ __forceinline__ void prefetch_l2(const void* p) {
    asm volatile("prefetch.global.L2 [%0];" :: "l"(p));
}

__device__ __forceinline__ void stwt128(float* p, float4 v) {
    asm volatile("st.global.wt.v4.f32 [%0], {%1,%2,%3,%4};"
                 :: "l"(p), "f"(v.x), "f"(v.y), "f"(v.z), "f"(v.w) : "memory");
}

#define LDSM_X4_T(r0, r1, r2, r3, addr) \
    asm volatile("ldmatrix.sync.aligned.m8n8.x4.trans.shared.b16 {%0,%1,%2,%3}, [%4];" \
                 : "=r"(r0), "=r"(r1), "=r"(r2), "=r"(r3) : "r"(addr))

#define MMA_F16(d, a, b0_, b1_) \
    asm volatile("mma.sync.aligned.m16n8k16.row.col.f32.f16.f16.f32 " \
                 "{%0,%1,%2,%3}, {%4,%5,%6,%7}, {%8,%9}, {%0,%1,%2,%3};" \
                 : "+f"((d)[0]), "+f"((d)[1]), "+f"((d)[2]), "+f"((d)[3]) \
                 : "r"((a)[0]), "r"((a)[1]), "r"((a)[2]), "r"((a)[3]), \
                   "r"(b0_), "r"(b1_))

extern "C" __global__ void __launch_bounds__(THREADS, 5)
parts_f16_burst_kernel(const float* __restrict__ x,
                       const float* __restrict__ W,
                       const float* __restrict__ bias,
                       float* __restrict__ out)
{
    extern __shared__ char smem[];
    const uint32_t sb = smem_u32(smem);
    const int t    = threadIdx.x;
    const int wid  = t >> 5;
    const int lane = t & 31;
    const int p    = blockIdx.y;
    const int b0   = blockIdx.x * BLOCK_B;

    const int w32  = wid * 32;
    const int qrow = lane >> 2;          // 0..7
    const int q4   = (lane & 3) * 4;     // phys-k / out-col quad offset

    const size_t RS = (size_t)(PP * KK); // 4096 floats, batch row stride

    // Per-thread A base: phys cols q4..q4+3 of each 16-k chunk.
    const float* xq = x + (size_t)(b0 + w32 + qrow) * RS + p * KK + q4;

    // ---- L2-prefetch ALL four chunks (full 128B lines, 2 per row-pair) ----
    #pragma unroll
    for (int mi = 0; mi < 2; mi++)
        #pragma unroll
        for (int rs = 0; rs < 2; rs++) {
            prefetch_l2(xq + (mi * 16 + rs * 8) * RS);
            prefetch_l2(xq + (mi * 16 + rs * 8) * RS + 32);
        }

    // ---- W[p] -> smem fp16, sigma/tau permuted ----
    // sigma: phys k -> smem row sr = (k&~15) + 2*((k>>2)&3) + (k&1) + 8*((k>>1)&1)
    // tau:   phys o (=c4*4+j) -> smem col (2*(c4>>2)+(j>>1))*8 + 2*(c4&3) + (j&1)
    #pragma unroll
    for (int i = 0; i < 8; i++) {
        int idx4 = i * 128 + t;
        int k    = idx4 >> 4;
        int c4   = idx4 & 15;
        float4 v = *(const float4*)(W + p * (KK * OO) + k * OO + c4 * 4);
        uint32_t h0 = pack_f16(v.x, v.y);
        uint32_t h1 = pack_f16(v.z, v.w);
        int w  = k & 15;
        int sr = (k & ~15) + 2 * (w >> 2) + (w & 1) + 8 * ((w >> 1) & 1);
        int col0 = (2 * (c4 >> 2)) * 8 + 2 * (c4 & 3);   // f16 units, pair j=0,1
        int col1 = col0 + 8;                              // pair j=2,3
        uint32_t base = (uint32_t)(sr * ROWB);
        *(uint32_t*)(smem + base + col0 * 2) = h0;
        *(uint32_t*)(smem + base + col1 * 2) = h1;
    }
    __syncthreads();

    // ---- Mainloop: 2 macro-iters, each = 8-LDG burst + 2 chunks compute ----
    const int lrow  = lane & 15;
    const int lcol8 = (lane >> 4) * 8;

    float acc[2][8][4];
    #pragma unroll
    for (int mi = 0; mi < 2; mi++)
        #pragma unroll
        for (int ni = 0; ni < 8; ni++)
            #pragma unroll
            for (int r = 0; r < 4; r++)
                acc[mi][ni][r] = 0.0f;

    #pragma unroll
    for (int half = 0; half < 2; half++) {
        // Burst-load chunks 2*half and 2*half+1 (full 128B line per row).
        float4 xf[2][2][2];   // [parity][mi][rs]
        #pragma unroll
        for (int mi = 0; mi < 2; mi++)
            #pragma unroll
            for (int rs = 0; rs < 2; rs++) {
                const float* base = xq + (mi * 16 + rs * 8) * RS + half * 32;
                xf[0][mi][rs] = *(const float4*)(base);
                xf[1][mi][rs] = *(const float4*)(base + 16);
            }

        #pragma unroll
        for (int par = 0; par < 2; par++) {
            const int ks = half * 2 + par;
            const int k0 = ks * 16;

            // a0 <- (rs0).xy, a1 <- (rs1).xy, a2 <- (rs0).zw, a3 <- (rs1).zw
            uint32_t ah[2][4];
            #pragma unroll
            for (int mi = 0; mi < 2; mi++) {
                ah[mi][0] = pack_f16(xf[par][mi][0].x, xf[par][mi][0].y);
                ah[mi][1] = pack_f16(xf[par][mi][1].x, xf[par][mi][1].y);
                ah[mi][2] = pack_f16(xf[par][mi][0].z, xf[par][mi][0].w);
                ah[mi][3] = pack_f16(xf[par][mi][1].z, xf[par][mi][1].w);
            }

            #pragma unroll
            for (int ng = 0; ng < 4; ng++) {
                uint32_t bh[4];
                uint32_t off = (uint32_t)((k0 + lrow) * ROWB
                                          + (ng * 16 + lcol8) * 2);
                LDSM_X4_T(bh[0], bh[1], bh[2], bh[3], sb + off);

                #pragma unroll
                for (int mi = 0; mi < 2; mi++) {
                    MMA_F16(acc[mi][2 * ng + 0], ah[mi], bh[0], bh[1]);
                    MMA_F16(acc[mi][2 * ng + 1], ah[mi], bh[2], bh[3]);
                }
            }
        }
    }

    // ---- Epilogue (tau): thread owns out cols g*16 + q4 .. +3 ----
    float4 bv[4];
    #pragma unroll
    for (int g = 0; g < 4; g++)
        bv[g] = *(const float4*)(bias + p * OO + g * 16 + q4);

    #pragma unroll
    for (int mi = 0; mi < 2; mi++) {
        #pragma unroll
        for (int rs = 0; rs < 2; rs++) {
            const int row = b0 + w32 + mi * 16 + rs * 8 + qrow;
            float* op = out + (size_t)row * RS + p * OO + q4;
            #pragma unroll
            for (int g = 0; g < 4; g++) {
                float4 v;
                v.x = fmaxf(acc[mi][2 * g + 0][rs * 2 + 0] + bv[g].x, 0.0f);
                v.y = fmaxf(acc[mi][2 * g + 0][rs * 2 + 1] + bv[g].y, 0.0f);
                v.z = fmaxf(acc[mi][2 * g + 1][rs * 2 + 0] + bv[g].z, 0.0f);
                v.w = fmaxf(acc[mi][2 * g + 1][rs * 2 + 1] + bv[g].w, 0.0f);
                stwt128(op + g * 16, v);
            }
        }
    }
}

extern "C" void kernel_launch(void* const* d_in, const int* in_sizes, int n_in,
                              void* d_out, int out_size)
{
    const float* x    = (const float*)d_in[0];
    const float* W    = (const float*)d_in[1];
    const float* bias = (const float*)d_in[2];
    float* out = (float*)d_out;

    const int B = in_sizes[0] / (PP * KK);   // 16384

    cudaFuncSetAttribute(parts_f16_burst_kernel,
                         cudaFuncAttributeMaxDynamicSharedMemorySize, SM_TOTAL);

    dim3 grid(B / BLOCK_B, PP);
    parts_f16_burst_kernel<<<grid, THREADS, SM_TOTAL>>>(x, W, bias, out);
}

// round 16
// speedup vs baseline: 1.1007x; 1.0613x over previous
#include <cuda_runtime.h>
#include <cuda_fp16.h>
#include <cstdint>

// out[b,p,o] = relu(sum_k x[b,p,k] * W[p,k,o] + bias[p,o])
// B=16384, P=K=O=64 fp32.
// CTA = 128 b-rows x one part p, 4 warps, warp tile M=32,N=64.
// SINGLE-TERM fp16 (rel_err ~2.9e-4), fp32 accum, mma.sync.m16n8k16.
// sigma/tau permutations (LDG.128 A-loads, STG.128 C-stores), st.global.wt out.
// Two-chunk x load bursts (R15). R16: grid dims SWAPPED (p fast) so the
// concurrently-resident CTA window covers contiguous ~2MB regions densely
// (dense DRAM page coverage) instead of sparse 256B-per-16KB slices.

#define PP 64
#define KK 64
#define OO 64
#define BLOCK_B 128
#define THREADS 128

#define ASTRIDE 72                         // fp16 elems per smem row (144 B)
#define ROWB (ASTRIDE * 2)                 // 144 bytes per smem row
#define SW_BYTES (KK * ROWB)               // 9216
#define SM_TOTAL SW_BYTES

__device__ __forceinline__ uint32_t smem_u32(const void* p) {
    uint32_t a;
    asm("{ .reg .u64 t; cvta.to.shared.u64 t, %1; cvt.u32.u64 %0, t; }" : "=r"(a) : "l"(p));
    return a;
}

// pack word: lo16 = f16(a), hi16 = f16(b)
__device__ __forceinline__ uint32_t pack_f16(float a, float b) {
    uint32_t r;
    asm("cvt.rn.f16x2.f32 %0, %1, %2;" : "=r"(r) : "f"(b), "f"(a));
    return r;
}

__device__ __forceinline__ void prefetch_l2(const void* p) {
    asm volatile("prefetch.global.L2 [%0];" :: "l"(p));
}

__device__ __forceinline__ void stwt128(float* p, float4 v) {
    asm volatile("st.global.wt.v4.f32 [%0], {%1,%2,%3,%4};"
                 :: "l"(p), "f"(v.x), "f"(v.y), "f"(v.z), "f"(v.w) : "memory");
}

#define LDSM_X4_T(r0, r1, r2, r3, addr) \
    asm volatile("ldmatrix.sync.aligned.m8n8.x4.trans.shared.b16 {%0,%1,%2,%3}, [%4];" \
                 : "=r"(r0), "=r"(r1), "=r"(r2), "=r"(r3) : "r"(addr))

#define MMA_F16(d, a, b0_, b1_) \
    asm volatile("mma.sync.aligned.m16n8k16.row.col.f32.f16.f16.f32 " \
                 "{%0,%1,%2,%3}, {%4,%5,%6,%7}, {%8,%9}, {%0,%1,%2,%3};" \
                 : "+f"((d)[0]), "+f"((d)[1]), "+f"((d)[2]), "+f"((d)[3]) \
                 : "r"((a)[0]), "r"((a)[1]), "r"((a)[2]), "r"((a)[3]), \
                   "r"(b0_), "r"(b1_))

extern "C" __global__ void __launch_bounds__(THREADS, 5)
parts_f16_swap_kernel(const float* __restrict__ x,
                      const float* __restrict__ W,
                      const float* __restrict__ bias,
                      float* __restrict__ out)
{
    extern __shared__ char smem[];
    const uint32_t sb = smem_u32(smem);
    const int t    = threadIdx.x;
    const int wid  = t >> 5;
    const int lane = t & 31;
    const int p    = blockIdx.x;               // p is the FAST grid dim now
    const int b0   = blockIdx.y * BLOCK_B;

    const int w32  = wid * 32;
    const int qrow = lane >> 2;          // 0..7
    const int q4   = (lane & 3) * 4;     // phys-k / out-col quad offset

    const size_t RS = (size_t)(PP * KK); // 4096 floats, batch row stride

    // Per-thread A base: phys cols q4..q4+3 of each 16-k chunk.
    const float* xq = x + (size_t)(b0 + w32 + qrow) * RS + p * KK + q4;

    // ---- L2-prefetch ALL four chunks (full 128B lines, 2 per row-pair) ----
    #pragma unroll
    for (int mi = 0; mi < 2; mi++)
        #pragma unroll
        for (int rs = 0; rs < 2; rs++) {
            prefetch_l2(xq + (mi * 16 + rs * 8) * RS);
            prefetch_l2(xq + (mi * 16 + rs * 8) * RS + 32);
        }

    // ---- W[p] -> smem fp16, sigma/tau permuted ----
    // sigma: phys k -> smem row sr = (k&~15) + 2*((k>>2)&3) + (k&1) + 8*((k>>1)&1)
    // tau:   phys o (=c4*4+j) -> smem col (2*(c4>>2)+(j>>1))*8 + 2*(c4&3) + (j&1)
    #pragma unroll
    for (int i = 0; i < 8; i++) {
        int idx4 = i * 128 + t;
        int k    = idx4 >> 4;
        int c4   = idx4 & 15;
        float4 v = *(const float4*)(W + p * (KK * OO) + k * OO + c4 * 4);
        uint32_t h0 = pack_f16(v.x, v.y);
        uint32_t h1 = pack_f16(v.z, v.w);
        int w  = k & 15;
        int sr = (k & ~15) + 2 * (w >> 2) + (w & 1) + 8 * ((w >> 1) & 1);
        int col0 = (2 * (c4 >> 2)) * 8 + 2 * (c4 & 3);   // f16 units, pair j=0,1
        int col1 = col0 + 8;                              // pair j=2,3
        uint32_t base = (uint32_t)(sr * ROWB);
        *(uint32_t*)(smem + base + col0 * 2) = h0;
        *(uint32_t*)(smem + base + col1 * 2) = h1;
    }
    __syncthreads();

    // ---- Mainloop: 2 macro-iters, each = 8-LDG burst + 2 chunks compute ----
    const int lrow  = lane & 15;
    const int lcol8 = (lane >> 4) * 8;

    float acc[2][8][4];
    #pragma unroll
    for (int mi = 0; mi < 2; mi++)
        #pragma unroll
        for (int ni = 0; ni < 8; ni++)
            #pragma unroll
            for (int r = 0; r < 4; r++)
                acc[mi][ni][r] = 0.0f;

    #pragma unroll
    for (int half = 0; half < 2; half++) {
        // Burst-load chunks 2*half and 2*half+1 (full 128B line per row).
        float4 xf[2][2][2];   // [parity][mi][rs]
        #pragma unroll
        for (int mi = 0; mi < 2; mi++)
            #pragma unroll
            for (int rs = 0; rs < 2; rs++) {
                const float* base = xq + (mi * 16 + rs * 8) * RS + half * 32;
                xf[0][mi][rs] = *(const float4*)(base);
                xf[1][mi][rs] = *(const float4*)(base + 16);
            }

        #pragma unroll
        for (int par = 0; par < 2; par++) {
            const int ks = half * 2 + par;
            const int k0 = ks * 16;

            // a0 <- (rs0).xy, a1 <- (rs1).xy, a2 <- (rs0).zw, a3 <- (rs1).zw
            uint32_t ah[2][4];
            #pragma unroll
            for (int mi = 0; mi < 2; mi++) {
                ah[mi][0] = pack_f16(xf[par][mi][0].x, xf[par][mi][0].y);
                ah[mi][1] = pack_f16(xf[par][mi][1].x, xf[par][mi][1].y);
                ah[mi][2] = pack_f16(xf[par][mi][0].z, xf[par][mi][0].w);
                ah[mi][3] = pack_f16(xf[par][mi][1].z, xf[par][mi][1].w);
            }

            #pragma unroll
            for (int ng = 0; ng < 4; ng++) {
                uint32_t bh[4];
                uint32_t off = (uint32_t)((k0 + lrow) * ROWB
                                          + (ng * 16 + lcol8) * 2);
                LDSM_X4_T(bh[0], bh[1], bh[2], bh[3], sb + off);

                #pragma unroll
                for (int mi = 0; mi < 2; mi++) {
                    MMA_F16(acc[mi][2 * ng + 0], ah[mi], bh[0], bh[1]);
                    MMA_F16(acc[mi][2 * ng + 1], ah[mi], bh[2], bh[3]);
                }
            }
        }
    }

    // ---- Epilogue (tau): thread owns out cols g*16 + q4 .. +3 ----
    float4 bv[4];
    #pragma unroll
    for (int g = 0; g < 4; g++)
        bv[g] = *(const float4*)(bias + p * OO + g * 16 + q4);

    #pragma unroll
    for (int mi = 0; mi < 2; mi++) {
        #pragma unroll
        for (int rs = 0; rs < 2; rs++) {
            const int row = b0 + w32 + mi * 16 + rs * 8 + qrow;
            float* op = out + (size_t)row * RS + p * OO + q4;
            #pragma unroll
            for (int g = 0; g < 4; g++) {
                float4 v;
                v.x = fmaxf(acc[mi][2 * g + 0][rs * 2 + 0] + bv[g].x, 0.0f);
                v.y = fmaxf(acc[mi][2 * g + 0][rs * 2 + 1] + bv[g].y, 0.0f);
                v.z = fmaxf(acc[mi][2 * g + 1][rs * 2 + 0] + bv[g].z, 0.0f);
                v.w = fmaxf(acc[mi][2 * g + 1][rs * 2 + 1] + bv[g].w, 0.0f);
                stwt128(op + g * 16, v);
            }
        }
    }
}

extern "C" void kernel_launch(void* const* d_in, const int* in_sizes, int n_in,
                              void* d_out, int out_size)
{
    const float* x    = (const float*)d_in[0];
    const float* W    = (const float*)d_in[1];
    const float* bias = (const float*)d_in[2];
    float* out = (float*)d_out;

    const int B = in_sizes[0] / (PP * KK);   // 16384

    cudaFuncSetAttribute(parts_f16_swap_kernel,
                         cudaFuncAttributeMaxDynamicSharedMemorySize, SM_TOTAL);

    dim3 grid(PP, B / BLOCK_B);              // p fast, b-tile slow
    parts_f16_swap_kernel<<<grid, THREADS, SM_TOTAL>>>(x, W, bias, out);
}